// round 14
// baseline (speedup 1.0000x reference)
#include <cuda_runtime.h>
#include <cstdint>

#define Bdim 32
#define Kdim 17
#define Hdim 160
#define Wdim 160
#define HW   (Hdim*Wdim)
#define NG   (HW/4)
#define Pn   30
#define Sn   10
#define Ln   19
#define NCH  (Bdim*Kdim)
#define NBL  (Bdim*Ln)
#define GRIDF 296
#define TF   512
#define NSTRIP 20
#define SPX   8
#define RPB   10
#define ACT   (NSTRIP*16)
#define NBINS 1024
#define SCAP  128
#define NEGF  (-1.0e30f)

__constant__ int c_skel_a[Ln] = {15,13,16,14,11, 5, 6, 5, 5, 6, 7, 8, 1, 0, 0, 1, 2, 3, 4};
__constant__ int c_skel_b[Ln] = {13,11,14,12,12,11,12, 6, 7, 8, 9,10, 2, 1, 2, 3, 4, 5, 6};

__device__ int g_flag[NCH];          // zeroed by init_kernel each launch

// ---------------- cp.async helpers ----------------
__device__ __forceinline__ void cp16(void* s, const void* g) {
    unsigned sa = (unsigned)__cvta_generic_to_shared(s);
    asm volatile("cp.async.cg.shared.global [%0], [%1], 16;\n" :: "r"(sa), "l"(g));
}
__device__ __forceinline__ void cp_commit() { asm volatile("cp.async.commit_group;\n"); }
template <int N>
__device__ __forceinline__ void cp_wait() { asm volatile("cp.async.wait_group %0;\n" :: "n"(N)); }

__device__ __forceinline__ int bin_of(float h) {
    float h2 = h * h;
    float h4 = h2 * h2;
    float v  = h4 * h4 * h;          // h^9: uniform-izes max-of-9 peak scores
    int b = (int)(v * (float)NBINS);
    return b < 0 ? 0 : (b > NBINS - 1 ? NBINS - 1 : b);
}

__device__ __forceinline__ float max3(float a, float b, float c) {
    return fmaxf(fmaxf(a, b), c);
}

__device__ __forceinline__ const float4* chan_ptr(const float* paf, int bl, int c) {
    int b = bl / Ln;
    int l = bl - b * Ln;
    return (const float4*)(paf + ((size_t)b * 38 + 2 * l + c) * HW);
}

// load one row of an 8px strip: 2 contiguous float4 + 2 edge scalars.
__device__ __forceinline__ void loadrow8(const float* __restrict__ hp,
                                         int y, int x0, bool lf, bool rt,
                                         float rm[8], float px[8])
{
    if (y < 0 || y >= Hdim) {
        #pragma unroll
        for (int j = 0; j < SPX; ++j) { rm[j] = NEGF; px[j] = NEGF; }
        return;
    }
    const float4* p4 = (const float4*)(hp + y * Wdim + x0);
    float4 A = __ldg(p4);
    float4 B = __ldg(p4 + 1);
    float w[SPX + 2];
    w[0] = lf ? __ldg(hp + y * Wdim + x0 - 1) : NEGF;
    w[1] = A.x; w[2] = A.y; w[3] = A.z; w[4] = A.w;
    w[5] = B.x; w[6] = B.y; w[7] = B.z; w[8] = B.w;
    w[9] = rt ? __ldg(hp + y * Wdim + x0 + SPX) : NEGF;
    #pragma unroll
    for (int j = 0; j < SPX; ++j) {
        px[j] = w[j + 1];
        rm[j] = max3(w[j], w[j + 1], w[j + 2]);
    }
}

__global__ void init_kernel() {
    if (threadIdx.x < NCH) g_flag[threadIdx.x] = 0;
}

// ---------------------------------------------------------------------------
// Fused persistent kernel: 296 blocks (2/SM, fully resident).
//  - prefetch first limb PAF-x at start (overlaps all of stage1 with DRAM)
//  - stage1 for 1-2 channels -> peaks + release flag
//  - stage2 for 2-3 limbs, gated per-limb on the two channel flags
// ---------------------------------------------------------------------------
__global__ void __launch_bounds__(TF, 2) fused_kernel(const float* __restrict__ heat,
                                                      const float* __restrict__ paf,
                                                      float* __restrict__ out)
{
    extern __shared__ float buf[];               // HW floats: PAF channel buffer

    __shared__ unsigned hist[NBINS];
    __shared__ unsigned long long surv[SCAP];
    __shared__ unsigned long long s_top[Pn];
    __shared__ int s_sc, s_cut;
    __shared__ float sax[Pn], say[Pn], sas[Pn];
    __shared__ float sbx[Pn], sby[Pn], sbs[Pn];

    float* peaks = out;
    float* conn  = out + (size_t)NCH * Pn * 3;

    const int bid = blockIdx.x;
    const int tid = threadIdx.x;
    const int lane = tid & 31;

    // ---- prefetch first limb's x-channel (runs under all of stage1) ----
    {
        const float4* gx = chan_ptr(paf, bid, 0);
        for (int i = tid; i < NG; i += TF) cp16(&((float4*)buf)[i], gx + i);
        cp_commit();
    }

    // =======================  STAGE 1 (1-2 channels)  =======================
    for (int cpass = 0; cpass < 2; ++cpass) {
        const int ch = (cpass == 0) ? bid : (bid < NCH - GRIDF ? GRIDF + bid : -1);
        if (ch < 0) break;
        const float* hp = heat + (size_t)ch * HW;

        for (int i = tid; i < NBINS; i += TF) hist[i] = 0;
        if (tid == 0) { s_sc = 0; s_cut = 0; }
        __syncthreads();

        // pass 1: strip sweep, peaks -> bitmask + histogram
        unsigned b0 = 0, b1 = 0, b2 = 0;
        int x0 = 0, y0 = 0;
        if (tid < ACT) {
            const int strip = tid % NSTRIP;
            const int band  = tid / NSTRIP;
            x0 = strip * SPX;
            y0 = band * RPB;
            const bool lf = (strip > 0);
            const bool rt = (strip < NSTRIP - 1);

            float rmU[SPX], rmC[SPX], rmD[SPX];
            float C8[SPX], D8[SPX];
            loadrow8(hp, y0 - 1, x0, lf, rt, rmU, D8);
            loadrow8(hp, y0,     x0, lf, rt, rmC, C8);

            #pragma unroll 2
            for (int r = 0; r < RPB; ++r) {
                loadrow8(hp, y0 + r + 1, x0, lf, rt, rmD, D8);
                unsigned pat = 0;
                #pragma unroll
                for (int j = 0; j < SPX; ++j) {
                    float h = C8[j];
                    if (h > 0.1f && h >= rmU[j] && h >= rmC[j] && h >= rmD[j]) {
                        pat |= (1u << j);
                        atomicAdd(&hist[bin_of(h)], 1u);
                    }
                }
                if (r < 4)      b0 |= pat << (r * 8);
                else if (r < 8) b1 |= pat << ((r - 4) * 8);
                else            b2 |= pat << ((r - 8) * 8);
                #pragma unroll
                for (int j = 0; j < SPX; ++j) {
                    rmU[j] = rmC[j]; rmC[j] = rmD[j]; C8[j] = D8[j];
                }
            }
        }
        __syncthreads();

        // warp 0: cutoff bin = highest bin whose suffix count >= Pn
        if (tid < 32) {
            int acc = 0, cut = 0;
            for (int base = NBINS - 32; base >= 0; base -= 32) {
                int s = (int)hist[base + lane];
                #pragma unroll
                for (int off = 1; off < 32; off <<= 1) {
                    int t = __shfl_down_sync(0xffffffffu, s, off);
                    if (lane + off < 32) s += t;
                }
                int chunk_total = __shfl_sync(0xffffffffu, s, 0);
                if (acc + chunk_total >= Pn) {
                    unsigned msk = __ballot_sync(0xffffffffu, acc + s >= Pn);
                    cut = base + (31 - __clz(msk));
                    break;
                }
                acc += chunk_total;
            }
            if (lane == 0) s_cut = cut;
        }
        __syncthreads();

        // pass 2: bitmask replay, keep bins >= cut (~33/block -> cheap atomics)
        const int cut = s_cut;
        if (tid < ACT) {
            unsigned mw[3] = {b0, b1, b2};
            #pragma unroll
            for (int w = 0; w < 3; ++w) {
                unsigned m = mw[w];
                while (m) {
                    int bit = __ffs(m) - 1;
                    m &= m - 1;
                    int rr = (w * 32 + bit) >> 3;
                    int j  = (w * 32 + bit) & 7;
                    unsigned idx = (unsigned)((y0 + rr) * Wdim + x0 + j);
                    float h = __ldg(hp + idx);
                    if (bin_of(h) >= cut) {
                        int pos = atomicAdd(&s_sc, 1);
                        if (pos < SCAP)
                            surv[pos] = ((unsigned long long)__float_as_uint(h) << 32) |
                                        (unsigned long long)(0xFFFFFFFFu - idx);
                    }
                }
            }
        }
        __syncthreads();

        // warp 0: register-resident top-30 (4 keys/lane, butterfly max)
        if (tid < 32) {
            const int n = (s_sc < SCAP) ? s_sc : SCAP;
            unsigned long long v0 = (lane      < n) ? surv[lane]      : 0ull;
            unsigned long long v1 = (lane + 32 < n) ? surv[lane + 32] : 0ull;
            unsigned long long v2 = (lane + 64 < n) ? surv[lane + 64] : 0ull;
            unsigned long long v3 = (lane + 96 < n) ? surv[lane + 96] : 0ull;
            for (int p = 0; p < Pn; ++p) {
                unsigned long long m01 = v0 > v1 ? v0 : v1;
                unsigned long long m23 = v2 > v3 ? v2 : v3;
                unsigned long long m = m01 > m23 ? m01 : m23;
                #pragma unroll
                for (int off = 16; off > 0; off >>= 1) {
                    unsigned long long o = __shfl_xor_sync(0xffffffffu, m, off);
                    if (o > m) m = o;
                }
                if (lane == 0) s_top[p] = m;
                if      (v0 == m) v0 = 0ull;
                else if (v1 == m) v1 = 0ull;
                else if (v2 == m) v2 = 0ull;
                else if (v3 == m) v3 = 0ull;
            }
            __syncwarp();

            // subpixel refine + emit (lanes 0..29)
            if (lane < Pn) {
                unsigned long long key = s_top[lane];
                float px = 0.f, py = 0.f, sc = 0.f;
                if (key != 0ull) {
                    unsigned idx = 0xFFFFFFFFu - (unsigned)(key & 0xFFFFFFFFu);
                    float h = __uint_as_float((unsigned)(key >> 32));
                    int y = idx / Wdim;
                    int x = idx - y * Wdim;
                    float dx = 0.f, dy = 0.f;
                    if (y > 0 && y < Hdim - 1 && x > 0 && x < Wdim - 1) {
                        float r = __ldg(hp + idx + 1),    l = __ldg(hp + idx - 1);
                        float d = __ldg(hp + idx + Wdim), u = __ldg(hp + idx - Wdim);
                        float dxr = 0.5f * (r - l);
                        float dxx = (r + l) - 2.0f * h;
                        dx = (fabsf(dxx) > 1e-6f) ? (dxr / (-dxx)) : dxr;
                        float dyr = 0.5f * (d - u);
                        float dyy = (d + u) - 2.0f * h;
                        dy = (fabsf(dyy) > 1e-6f) ? (dyr / (-dyy)) : dyr;
                    }
                    px = (float)x + dx;
                    py = (float)y + dy;
                    sc = h;
                }
                float* o = peaks + ((size_t)ch * Pn + lane) * 3;
                o[0] = px; o[1] = py; o[2] = sc;
            }
            __threadfence();                     // peaks visible before flag
            __syncwarp();
            if (lane == 0) atomicExch(&g_flag[ch], 1);
        }
        __syncthreads();
    }

    // =======================  STAGE 2 (2-3 limbs)  =========================
    const float step = 1.0f / 9.0f;
    int limbs[3];
    limbs[0] = bid;
    limbs[1] = bid + GRIDF;                                  // < 608 always
    limbs[2] = (bid >= 248 && bid < 248 + (NBL - 2 * GRIDF)) // blocks 248..263
               ? 2 * GRIDF + (bid - 248) : -1;

    for (int t = 0; t < 3; ++t) {
        const int bl = limbs[t];
        if (bl < 0) break;
        const int b = bl / Ln;
        const int l = bl - b * Ln;
        const int cha = b * Kdim + c_skel_a[l];
        const int chb = b * Kdim + c_skel_b[l];

        if (tid == 0) {
            while (atomicAdd(&g_flag[cha], 0) == 0) {}
            while (atomicAdd(&g_flag[chb], 0) == 0) {}
        }
        __syncthreads();

        if (tid < Pn) {
            const float* pa = peaks + ((size_t)cha * Pn + tid) * 3;
            sax[tid] = pa[0]; say[tid] = pa[1]; sas[tid] = pa[2];
        } else if (tid >= 32 && tid < 32 + Pn) {
            int j = tid - 32;
            const float* pb = peaks + ((size_t)chb * Pn + j) * 3;
            sbx[j] = pb[0]; sby[j] = pb[1]; sbs[j] = pb[2];
        }
        cp_wait<0>();                // x-channel resident
        __syncthreads();

        int   lin[2][Sn];
        float xp [2][Sn];
        float vyv[2];
        float halfs[2];
        bool  pv[2];

        #pragma unroll
        for (int q = 0; q < 2; ++q) {
            int pr = tid + q * TF;
            bool act = (pr < Pn * Pn);
            int i = act ? (pr / Pn) : 0;
            int j = act ? (pr - i * Pn) : 0;
            float ax = sax[i], ay = say[i], sa = sas[i];
            float bx = sbx[j], by = sby[j], sb = sbs[j];
            bool valid = act && (sa > 0.1f) && (sb > 0.1f);
            pv[q] = valid;
            halfs[q] = 0.5f * (sa + sb);
            float dxl = bx - ax;
            float dyl = by - ay;
            float norm = sqrtf(__fadd_rn(__fmul_rn(dxl, dxl), __fmul_rn(dyl, dyl))) + 1e-8f;
            float vx = dxl / norm;
            float vy = dyl / norm;
            vyv[q] = vy;
            #pragma unroll
            for (int s = 0; s < Sn; ++s) {
                float tt = (float)s * step;
                // no-FMA: a ulp flip at a .5 boundary changes the gathered cell
                float xs = __fadd_rn(ax, __fmul_rn(tt, dxl));
                float ys = __fadd_rn(ay, __fmul_rn(tt, dyl));
                float fx = fminf(fmaxf(rintf(xs), 0.0f), (float)(Wdim - 1));
                float fy = fminf(fmaxf(rintf(ys), 0.0f), (float)(Hdim - 1));
                int li = valid ? ((int)fy * Wdim + (int)fx) : 0;
                lin[q][s] = li;
                xp[q][s] = __fmul_rn(buf[li], vx);
            }
        }
        __syncthreads();             // x buffer consumed

        {
            const float4* gy = chan_ptr(paf, bl, 1);
            for (int i = tid; i < NG; i += TF) cp16(&((float4*)buf)[i], gy + i);
            cp_commit();
            cp_wait<0>();
        }
        __syncthreads();

        float* co = conn + (size_t)bl * Pn * Pn;
        #pragma unroll
        for (int q = 0; q < 2; ++q) {
            int pr = tid + q * TF;
            bool act = (pr < Pn * Pn);
            float sum = 0.0f;
            int c = 0;
            #pragma unroll
            for (int s = 0; s < Sn; ++s) {
                float v = __fadd_rn(xp[q][s], __fmul_rn(buf[lin[q][s]], vyv[q]));
                sum = __fadd_rn(sum, v);
                c += (v > 0.05f) ? 1 : 0;
            }
            float outv = 0.0f;
            if (pv[q]) {
                float mean = sum / 10.0f;
                float ratio = (float)c / 10.0f;
                if (mean > 0.0f && ratio > 0.8f)
                    outv = mean + halfs[q];
            }
            if (act) co[pr] = outv;
        }
        __syncthreads();             // y buffer consumed

        // prefetch next limb's x-channel
        int nx = (t + 1 < 3) ? limbs[t + 1] : -1;
        if (nx >= 0) {
            const float4* gx = chan_ptr(paf, nx, 0);
            for (int i = tid; i < NG; i += TF) cp16(&((float4*)buf)[i], gx + i);
            cp_commit();
        }
    }
}

// ---------------------------------------------------------------------------
extern "C" void kernel_launch(void* const* d_in, const int* in_sizes, int n_in,
                              void* d_out, int out_size)
{
    const float* heat = (const float*)d_in[0];
    const float* paf  = (const float*)d_in[1];
    float* out = (float*)d_out;

    const int smemf = HW * 4;        // 102400 dynamic -> 2 blocks/SM guaranteed
    cudaFuncSetAttribute(fused_kernel, cudaFuncAttributeMaxDynamicSharedMemorySize, smemf);

    init_kernel<<<1, NCH>>>();
    fused_kernel<<<GRIDF, TF, smemf>>>(heat, paf, out);
}